// round 4
// baseline (speedup 1.0000x reference)
#include <cuda_runtime.h>
#include <cuda_bf16.h>
#include <math.h>

// Problem constants
#define BB   32
#define INF  128
#define HH   1024
#define OUTF 128
#define KCAT (INF + HH)   // 1152
#define TPB  256

#define NT_L   4096                     // tiles (8 rows each) per H-output layer
#define NT_WO  512
#define NTILES (4 * NT_L + NT_WO)       // 16896
#define NCHUNK (NTILES / 2)             // 8448 (chunk = 2 tiles = 16 rows, never straddles layer/batch)

// Scratch (allocation-free rule: __device__ globals)
__device__ float    g_c0[BB * HH];
__device__ float    g_c1[BB * HH];
__device__ float    g_c2[BB * HH];
__device__ float    g_logits[BB * OUTF];
__device__ unsigned g_next;
__device__ unsigned g_done[4 * BB];     // [0]=L0,[1]=L1,[2]=L2 (count to 128), [3]=WO (count to 16)

__global__ void init_kernel() {
    if (threadIdx.x == 0) g_next = 0;
    if (threadIdx.x < 4 * BB) g_done[threadIdx.x] = 0;
}

// L2 prefetch of one W chunk (16 rows * K floats), ~1 line per thread.
__device__ __forceinline__ void prefetch_l2(const char* p, int bytes) {
    for (int i = threadIdx.x * 128; i < bytes; i += TPB * 128)
        asm volatile("prefetch.global.L2 [%0];" :: "l"(p + i));
}

// Process one chunk: 2 tiles = rows [rowbase, rowbase+16), one batch b.
// Each warp handles 2 rows. Activation already staged in xs.
template <int K>
__device__ __forceinline__ void chunk_compute(
    const float* __restrict__ W, const float* __restrict__ bias,
    float* __restrict__ outp, int Hout, int rowbase, int b,
    bool do_tanh, const float* __restrict__ xs)
{
    const int warp = threadIdx.x >> 5;
    const int lane = threadIdx.x & 31;
    const int r0 = rowbase + warp;
    const int r1 = rowbase + 8 + warp;

    const float4* __restrict__ Wr0 = reinterpret_cast<const float4*>(W + (size_t)r0 * K);
    const float4* __restrict__ Wr1 = reinterpret_cast<const float4*>(W + (size_t)r1 * K);
    const float4* __restrict__ xv  = reinterpret_cast<const float4*>(xs);

    float s0 = 0.f, s1 = 0.f;
#pragma unroll
    for (int j = 0; j < K / 128; j++) {
        float4 v = xv[j * 32 + lane];
        float4 a = __ldcs(Wr0 + j * 32 + lane);
        float4 c = __ldcs(Wr1 + j * 32 + lane);
        s0 += a.x * v.x + a.y * v.y + a.z * v.z + a.w * v.w;
        s1 += c.x * v.x + c.y * v.y + c.z * v.z + c.w * v.w;
    }
#pragma unroll
    for (int off = 16; off; off >>= 1) {
        s0 += __shfl_xor_sync(0xFFFFFFFFu, s0, off);
        s1 += __shfl_xor_sync(0xFFFFFFFFu, s1, off);
    }
    if (lane == 0) {
        int o0 = r0 - b * Hout;
        float v0 = s0 + bias[o0];
        float v1 = s1 + bias[o0 + 8];
        outp[r0] = do_tanh ? tanhf(v0) : v0;
        outp[r1] = do_tanh ? tanhf(v1) : v1;
        __threadfence();            // publish before the done-counter bump
    }
}

__global__ __launch_bounds__(TPB, 6) void fused_queue_kernel(
    const float* __restrict__ x,  const float* __restrict__ hidden,
    const float* __restrict__ W0, const float* __restrict__ b0,
    const float* __restrict__ W1, const float* __restrict__ b1,
    const float* __restrict__ W2, const float* __restrict__ b2,
    const float* __restrict__ Wh, const float* __restrict__ bh,
    const float* __restrict__ Wo, const float* __restrict__ bo,
    float* __restrict__ out, float* __restrict__ new_hidden)
{
    __shared__ float xs[KCAT];
    __shared__ int   s_chunk;

    const int tid = threadIdx.x;

    // ---- decode helper data --------------------------------------------
    auto decode_W = [&](int u, const float*& W, int& K) {
        if      (u < NT_L)     { W = W0; K = KCAT; }
        else if (u < 2 * NT_L) { W = W1; K = HH;   }
        else if (u < 3 * NT_L) { W = W2; K = HH;   }
        else if (u < 4 * NT_L) { W = Wh; K = HH;   }
        else                   { W = Wo; K = HH;   }
    };

    auto pull = [&]() -> int {
        __syncthreads();
        if (tid == 0) s_chunk = (int)atomicAdd(&g_next, 1u);
        __syncthreads();
        return s_chunk;
    };

    auto prefetch_chunk = [&](int c) {
        int u = c * 2;
        const float* W; int K;
        decode_W(u, W, K);
        int trel = u & (NT_L - 1);                 // works for WO too (512 < 4096)
        if (u >= 4 * NT_L) trel = u - 4 * NT_L;
        prefetch_l2((const char*)(W + (size_t)trel * 8 * K), 16 * K * 4);
    };

    // ---- main queue loop -------------------------------------------------
    int cur = pull();
    if (cur < NCHUNK) prefetch_chunk(cur);

    while (cur < NCHUNK) {
        int nxt = pull();
        if (nxt < NCHUNK) prefetch_chunk(nxt);

        // decode current chunk
        int u = cur * 2;
        int layer, trel;
        if      (u < NT_L)     { layer = 0; trel = u; }
        else if (u < 2 * NT_L) { layer = 1; trel = u - NT_L; }
        else if (u < 3 * NT_L) { layer = 2; trel = u - 2 * NT_L; }
        else if (u < 4 * NT_L) { layer = 3; trel = u - 3 * NT_L; }
        else                   { layer = 4; trel = u - 4 * NT_L; }
        const int rowbase = trel * 8;
        const int Hout = (layer == 4) ? OUTF : HH;
        const int b = rowbase / Hout;

        const float* W; const float* bias; const float* act; float* outp;
        int depIdx = -1, sigIdx = -1; unsigned depNeed = 128;
        switch (layer) {
            case 0: W = W0; bias = b0; act = nullptr; outp = g_c0;       sigIdx = 0 * BB + b; break;
            case 1: W = W1; bias = b1; act = g_c0;    outp = g_c1;       depIdx = 0 * BB + b; sigIdx = 1 * BB + b; break;
            case 2: W = W2; bias = b2; act = g_c1;    outp = g_c2;       depIdx = 1 * BB + b; sigIdx = 2 * BB + b; break;
            case 3: W = Wh; bias = bh; act = g_c2;    outp = new_hidden; depIdx = 2 * BB + b; break;
            case 4: W = Wo; bias = bo; act = g_c2;    outp = g_logits;   depIdx = 2 * BB + b; sigIdx = 3 * BB + b; break;
        }

        // dependency wait (steady state: already satisfied)
        if (tid == 0 && depIdx >= 0) {
            while (*(volatile unsigned*)&g_done[depIdx] < depNeed) __nanosleep(32);
            __threadfence();
        }
        __syncthreads();

        // stage activation vector for this batch into smem
        if (layer == 0) {
            const float4* xa = reinterpret_cast<const float4*>(x + (size_t)b * INF);
            const float4* xb = reinterpret_cast<const float4*>(hidden + (size_t)b * HH);
            for (int i = tid; i < KCAT / 4; i += TPB)
                reinterpret_cast<float4*>(xs)[i] =
                    (i < INF / 4) ? xa[i] : xb[i - INF / 4];
        } else {
            const float4* src = reinterpret_cast<const float4*>(act + (size_t)b * HH);
            for (int i = tid; i < HH / 4; i += TPB)
                reinterpret_cast<float4*>(xs)[i] = src[i];
        }
        __syncthreads();

        // compute 16 rows
        if (layer == 0)
            chunk_compute<KCAT>(W, bias, outp, Hout, rowbase, b, true, xs);
        else
            chunk_compute<HH>(W, bias, outp, Hout, rowbase, b, layer != 4, xs);

        // signal (2 tiles done)
        __syncthreads();
        if (tid == 0 && sigIdx >= 0) atomicAdd(&g_done[sigIdx], 2u);

        cur = nxt;
    }

    // ---- log_softmax tail: block bid<32 handles batch=bid with warp 0 ----
    if (blockIdx.x < BB && tid < 32) {
        const int bq = blockIdx.x;
        if (tid == 0) {
            while (*(volatile unsigned*)&g_done[3 * BB + bq] < 16u) __nanosleep(32);
            __threadfence();
        }
        __syncwarp();
        const int lane = tid;
        const float* l = g_logits + bq * OUTF;
        float v[4];
#pragma unroll
        for (int i = 0; i < 4; i++) v[i] = l[i * 32 + lane];
        float m = fmaxf(fmaxf(v[0], v[1]), fmaxf(v[2], v[3]));
#pragma unroll
        for (int off = 16; off; off >>= 1)
            m = fmaxf(m, __shfl_xor_sync(0xFFFFFFFFu, m, off));
        float ssum = 0.f;
#pragma unroll
        for (int i = 0; i < 4; i++) ssum += __expf(v[i] - m);
#pragma unroll
        for (int off = 16; off; off >>= 1)
            ssum += __shfl_xor_sync(0xFFFFFFFFu, ssum, off);
        float lse = m + logf(ssum);
#pragma unroll
        for (int i = 0; i < 4; i++)
            out[bq * OUTF + i * 32 + lane] = v[i] - lse;
    }
}

extern "C" void kernel_launch(void* const* d_in, const int* in_sizes, int n_in,
                              void* d_out, int out_size) {
    const float* x      = (const float*)d_in[0];
    const float* hidden = (const float*)d_in[1];
    const float* W0 = (const float*)d_in[2];
    const float* b0 = (const float*)d_in[3];
    const float* W1 = (const float*)d_in[4];
    const float* b1 = (const float*)d_in[5];
    const float* W2 = (const float*)d_in[6];
    const float* b2 = (const float*)d_in[7];
    const float* Wh = (const float*)d_in[8];
    const float* bh = (const float*)d_in[9];
    const float* Wo = (const float*)d_in[10];
    const float* bo = (const float*)d_in[11];

    float* out = (float*)d_out;                 // [B*OUT] log_softmax, then [B*H] new_hidden
    float* new_hidden = out + BB * OUTF;

    int dev = 0, sms = 0, occ = 0;
    cudaGetDevice(&dev);
    cudaDeviceGetAttribute(&sms, cudaDevAttrMultiProcessorCount, dev);
    cudaOccupancyMaxActiveBlocksPerMultiprocessor(&occ, fused_queue_kernel, TPB, 0);
    if (occ < 1) occ = 1;
    int nb = sms * occ;                         // all blocks resident -> queue is deadlock-free
    if (nb < BB) nb = BB;                       // softmax tail needs 32 blocks
    if (nb > NCHUNK) nb = NCHUNK;

    init_kernel<<<1, TPB>>>();
    fused_queue_kernel<<<nb, TPB>>>(x, hidden, W0, b0, W1, b1, W2, b2,
                                    Wh, bh, Wo, bo, out, new_hidden);

    (void)in_sizes; (void)n_in; (void)out_size;
}

// round 5
// speedup vs baseline: 1.1486x; 1.1486x over previous
#include <cuda_runtime.h>
#include <cuda_bf16.h>
#include <math.h>

// Problem constants
#define BB   32
#define INF  128
#define HH   1024
#define OUTF 128
#define KCAT (INF + HH)   // 1152
#define TPB  256

// Scratch (allocation-free rule: __device__ globals)
__device__ float g_c0[BB * HH];
__device__ float g_c1[BB * HH];
__device__ float g_c2[BB * HH];
__device__ float g_logits[BB * OUTF];

// ---------------------------------------------------------------------------
// Per-layer kernel, grid-stride over 16-row "pairs" (2 rows per warp).
// Each block owns a contiguous range of pairs -> same batch almost always,
// so the activation vector is staged into smem once per batch change.
// No per-chunk syncs in steady state; j-loop fully unrolled so ptxas keeps
// ~16 LDG.128s in flight per warp across iterations.
// ---------------------------------------------------------------------------
template <int K, bool TANH, bool CONCAT>
__global__ __launch_bounds__(TPB) void layer_kernel(
    const float* __restrict__ W, const float* __restrict__ bias,
    const float* __restrict__ inA, const float* __restrict__ inB,
    float* __restrict__ outp, int Hout, int npairs, int per)
{
    __shared__ float4 xs[K / 4];

    const int warp = threadIdx.x >> 5;
    const int lane = threadIdx.x & 31;

    int p0 = blockIdx.x * per;
    int p1 = min(p0 + per, npairs);
    int staged = -1;

    for (int p = p0; p < p1; ++p) {
        const int rowbase = p * 16;
        const int b = rowbase / Hout;   // 16 | Hout, never straddles a batch

        if (b != staged) {
            if (staged != -1) __syncthreads();   // protect xs readers
            if (CONCAT) {
                const float4* xa = reinterpret_cast<const float4*>(inA + (size_t)b * INF);
                const float4* xb = reinterpret_cast<const float4*>(inB + (size_t)b * HH);
                for (int i = threadIdx.x; i < K / 4; i += TPB)
                    xs[i] = (i < INF / 4) ? xa[i] : xb[i - INF / 4];
            } else {
                const float4* src = reinterpret_cast<const float4*>(inA + (size_t)b * K);
                for (int i = threadIdx.x; i < K / 4; i += TPB)
                    xs[i] = src[i];
            }
            __syncthreads();
            staged = b;
        }

        const int r0 = rowbase + warp;
        const int r1 = r0 + 8;
        const float4* __restrict__ Wr0 = reinterpret_cast<const float4*>(W + (size_t)r0 * K);
        const float4* __restrict__ Wr1 = reinterpret_cast<const float4*>(W + (size_t)r1 * K);

        float s0 = 0.f, s1 = 0.f;
#pragma unroll
        for (int j = 0; j < K / 128; j++) {
            float4 a = __ldcs(Wr0 + j * 32 + lane);
            float4 c = __ldcs(Wr1 + j * 32 + lane);
            float4 v = xs[j * 32 + lane];
            s0 += a.x * v.x + a.y * v.y + a.z * v.z + a.w * v.w;
            s1 += c.x * v.x + c.y * v.y + c.z * v.z + c.w * v.w;
        }
#pragma unroll
        for (int off = 16; off; off >>= 1) {
            s0 += __shfl_xor_sync(0xFFFFFFFFu, s0, off);
            s1 += __shfl_xor_sync(0xFFFFFFFFu, s1, off);
        }
        if (lane == 0) {
            const int o = r0 - b * Hout;
            float v0 = s0 + bias[o];
            float v1 = s1 + bias[o + 8];
            outp[r0] = TANH ? tanhf(v0) : v0;
            outp[r1] = TANH ? tanhf(v1) : v1;
        }
    }
}

// Heads: pairs [0, 2048) -> Wh (tanh -> new_hidden), [2048, 2304) -> Wo (logits).
__global__ __launch_bounds__(TPB) void heads_kernel(
    const float* __restrict__ Wh, const float* __restrict__ bh,
    const float* __restrict__ Wo, const float* __restrict__ bo,
    float* __restrict__ new_hidden, int npairs, int per)
{
    __shared__ float4 xs[HH / 4];

    const int warp = threadIdx.x >> 5;
    const int lane = threadIdx.x & 31;
    const int NP_H = (BB * HH) / 16;   // 2048

    int p0 = blockIdx.x * per;
    int p1 = min(p0 + per, npairs);
    int staged = -1;

    for (int p = p0; p < p1; ++p) {
        const bool is_h = (p < NP_H);
        const int Hout = is_h ? HH : OUTF;
        const int rowbase = (is_h ? p : (p - NP_H)) * 16;
        const int b = rowbase / Hout;
        const float* Wb   = is_h ? Wh : Wo;
        const float* bias = is_h ? bh : bo;
        float* outp       = is_h ? new_hidden : g_logits;

        if (b != staged) {   // same activation (g_c2) for both regions
            if (staged != -1) __syncthreads();
            const float4* src = reinterpret_cast<const float4*>(g_c2 + (size_t)b * HH);
            for (int i = threadIdx.x; i < HH / 4; i += TPB)
                xs[i] = src[i];
            __syncthreads();
            staged = b;
        }

        const int r0 = rowbase + warp;
        const int r1 = r0 + 8;
        const float4* __restrict__ Wr0 = reinterpret_cast<const float4*>(Wb + (size_t)r0 * HH);
        const float4* __restrict__ Wr1 = reinterpret_cast<const float4*>(Wb + (size_t)r1 * HH);

        float s0 = 0.f, s1 = 0.f;
#pragma unroll
        for (int j = 0; j < HH / 128; j++) {
            float4 a = __ldcs(Wr0 + j * 32 + lane);
            float4 c = __ldcs(Wr1 + j * 32 + lane);
            float4 v = xs[j * 32 + lane];
            s0 += a.x * v.x + a.y * v.y + a.z * v.z + a.w * v.w;
            s1 += c.x * v.x + c.y * v.y + c.z * v.z + c.w * v.w;
        }
#pragma unroll
        for (int off = 16; off; off >>= 1) {
            s0 += __shfl_xor_sync(0xFFFFFFFFu, s0, off);
            s1 += __shfl_xor_sync(0xFFFFFFFFu, s1, off);
        }
        if (lane == 0) {
            const int o = r0 - b * Hout;
            float v0 = s0 + bias[o];
            float v1 = s1 + bias[o + 8];
            if (is_h) { outp[r0] = tanhf(v0); outp[r1] = tanhf(v1); }
            else      { outp[r0] = v0;        outp[r1] = v1; }
        }
    }
}

// log_softmax over 128 logits per batch; one warp per batch row.
__global__ void log_softmax_kernel(float* __restrict__ out) {
    const int warp = threadIdx.x >> 5;   // 0..31 (single block of 1024)
    const int lane = threadIdx.x & 31;
    const float* l = g_logits + warp * OUTF;

    float v[4];
#pragma unroll
    for (int i = 0; i < 4; i++) v[i] = l[i * 32 + lane];

    float m = fmaxf(fmaxf(v[0], v[1]), fmaxf(v[2], v[3]));
#pragma unroll
    for (int off = 16; off; off >>= 1)
        m = fmaxf(m, __shfl_xor_sync(0xFFFFFFFFu, m, off));

    float s = 0.f;
#pragma unroll
    for (int i = 0; i < 4; i++) s += __expf(v[i] - m);
#pragma unroll
    for (int off = 16; off; off >>= 1)
        s += __shfl_xor_sync(0xFFFFFFFFu, s, off);

    float lse = m + logf(s);
#pragma unroll
    for (int i = 0; i < 4; i++)
        out[warp * OUTF + i * 32 + lane] = v[i] - lse;
}

extern "C" void kernel_launch(void* const* d_in, const int* in_sizes, int n_in,
                              void* d_out, int out_size) {
    const float* x      = (const float*)d_in[0];
    const float* hidden = (const float*)d_in[1];
    const float* W0 = (const float*)d_in[2];
    const float* b0 = (const float*)d_in[3];
    const float* W1 = (const float*)d_in[4];
    const float* b1 = (const float*)d_in[5];
    const float* W2 = (const float*)d_in[6];
    const float* b2 = (const float*)d_in[7];
    const float* Wh = (const float*)d_in[8];
    const float* bh = (const float*)d_in[9];
    const float* Wo = (const float*)d_in[10];
    const float* bo = (const float*)d_in[11];

    float* out = (float*)d_out;                 // [B*OUT] log_softmax, then [B*H] new_hidden
    float* new_hidden = out + BB * OUTF;

    float *c0, *c1, *c2;
    cudaGetSymbolAddress((void**)&c0, g_c0);
    cudaGetSymbolAddress((void**)&c1, g_c1);
    cudaGetSymbolAddress((void**)&c2, g_c2);

    int dev = 0, sms = 0, occ0 = 0, occ1 = 0, occh = 0;
    cudaGetDevice(&dev);
    cudaDeviceGetAttribute(&sms, cudaDevAttrMultiProcessorCount, dev);
    cudaOccupancyMaxActiveBlocksPerMultiprocessor(&occ0, layer_kernel<KCAT, true, true>, TPB, 0);
    cudaOccupancyMaxActiveBlocksPerMultiprocessor(&occ1, layer_kernel<HH, true, false>, TPB, 0);
    cudaOccupancyMaxActiveBlocksPerMultiprocessor(&occh, heads_kernel, TPB, 0);
    if (occ0 < 1) occ0 = 1; if (occ1 < 1) occ1 = 1; if (occh < 1) occh = 1;

    const int NP_L = (BB * HH) / 16;            // 2048 pairs per H layer
    const int NP_HEADS = NP_L + (BB * OUTF) / 16; // 2304

    // grid = resident capacity; per = ceil(pairs/grid)  (one "wave", long-lived blocks)
    int nb0 = sms * occ0; if (nb0 > NP_L) nb0 = NP_L;
    int per0 = (NP_L + nb0 - 1) / nb0;
    int nb1 = sms * occ1; if (nb1 > NP_L) nb1 = NP_L;
    int per1 = (NP_L + nb1 - 1) / nb1;
    int nbh = sms * occh; if (nbh > NP_HEADS) nbh = NP_HEADS;
    int perh = (NP_HEADS + nbh - 1) / nbh;

    layer_kernel<KCAT, true, true ><<<nb0, TPB>>>(W0, b0, x,  hidden, c0, HH, NP_L, per0);
    layer_kernel<HH,   true, false><<<nb1, TPB>>>(W1, b1, c0, nullptr, c1, HH, NP_L, per1);
    layer_kernel<HH,   true, false><<<nb1, TPB>>>(W2, b2, c1, nullptr, c2, HH, NP_L, per1);
    heads_kernel<<<nbh, TPB>>>(Wh, bh, Wo, bo, new_hidden, NP_HEADS, perh);
    log_softmax_kernel<<<1, BB * 32>>>(out);

    (void)in_sizes; (void)n_in; (void)out_size;
}